// round 5
// baseline (speedup 1.0000x reference)
#include <cuda_runtime.h>
#include <math.h>

#define BATCH 16
#define C_GMS 0.0026f

// ---------------- scratch (device globals; no allocation allowed) ----------
__device__ float d_g0[2][BATCH * 512 * 512];   // grayscale pyramid, both images
__device__ float d_g1[2][BATCH * 256 * 256];
__device__ float d_g2[2][BATCH * 128 * 128];
__device__ float d_g3[2][BATCH * 64 * 64];
__device__ float d_part[4][4096];              // per-block partial sums per scale

__device__ __forceinline__ float* gray_ptr(int s, int img) {
    switch (s) {
        case 0:  return d_g0[img];
        case 1:  return d_g1[img];
        case 2:  return d_g2[img];
        default: return d_g3[img];
    }
}

// ---------------- kernel 1: grayscale + first 2x2 avg-pool (fused) ---------
// One thread per gray1 pixel: reads a 2x2 RGB patch (vectorized float2),
// writes 4 gray0 pixels + 1 gray1 pixel.
__global__ void gray_pool_kernel(const float* __restrict__ Ii,
                                 const float* __restrict__ Ir) {
    const int img = blockIdx.z;
    const float* src = img ? Ir : Ii;
    float* g0 = d_g0[img];
    float* g1 = d_g1[img];

    int i = blockIdx.x * blockDim.x + threadIdx.x;
    if (i >= BATCH * 256 * 256) return;
    int w2 = i & 255;
    int t = i >> 8;
    int h2 = t & 255;
    int b = t >> 8;

    const long cs = 512L * 512L;
    const float* p = src + (long)b * 3 * cs + (long)(2 * h2) * 512 + 2 * w2;

    float2 r0c0 = *(const float2*)(p);
    float2 r1c0 = *(const float2*)(p + 512);
    float2 r0c1 = *(const float2*)(p + cs);
    float2 r1c1 = *(const float2*)(p + cs + 512);
    float2 r0c2 = *(const float2*)(p + 2 * cs);
    float2 r1c2 = *(const float2*)(p + 2 * cs + 512);

    const float inv3 = 1.0f / 3.0f;
    float g00 = (r0c0.x + r0c1.x + r0c2.x) * inv3;
    float g01 = (r0c0.y + r0c1.y + r0c2.y) * inv3;
    float g10 = (r1c0.x + r1c1.x + r1c2.x) * inv3;
    float g11 = (r1c0.y + r1c1.y + r1c2.y) * inv3;

    float* q = g0 + ((long)b * 512 + 2 * h2) * 512 + 2 * w2;
    *(float2*)q         = make_float2(g00, g01);
    *(float2*)(q + 512) = make_float2(g10, g11);

    g1[i] = (g00 + g01 + g10 + g11) * 0.25f;
}

// ---------------- kernel 2: generic 2x2 avg-pool on grayscale --------------
__global__ void pool_kernel(int s_in, int Hout, int Wout) {
    const int img = blockIdx.z;
    const float* in = gray_ptr(s_in, img);
    float* out = gray_ptr(s_in + 1, img);

    int i = blockIdx.x * blockDim.x + threadIdx.x;
    int n = BATCH * Hout * Wout;
    if (i >= n) return;
    int w = i % Wout;
    int t = i / Wout;
    int h = t % Hout;
    int b = t / Hout;
    int Win = Wout * 2;

    const float* p = in + ((long)b * Hout * 2 + 2 * h) * Win + 2 * w;
    float2 a = *(const float2*)p;
    float2 c = *(const float2*)(p + Win);
    out[i] = (a.x + a.y + c.x + c.y) * 0.25f;
}

// ---------------- median-of-9 min/max network ------------------------------
__device__ __forceinline__ void mnmx(float& a, float& b) {
    float t = fminf(a, b);
    b = fmaxf(a, b);
    a = t;
}
__device__ __forceinline__ float med9(float p0, float p1, float p2,
                                      float p3, float p4, float p5,
                                      float p6, float p7, float p8) {
    mnmx(p1, p2); mnmx(p4, p5); mnmx(p7, p8);
    mnmx(p0, p1); mnmx(p3, p4); mnmx(p6, p7);
    mnmx(p1, p2); mnmx(p4, p5); mnmx(p7, p8);
    mnmx(p0, p3); mnmx(p5, p8); mnmx(p4, p7);
    mnmx(p3, p6); mnmx(p1, p4); mnmx(p2, p5);
    mnmx(p4, p7); mnmx(p4, p2); mnmx(p6, p4);
    mnmx(p4, p2);
    return p4;
}

// ---------------- kernel 3: fused median3 + Prewitt + GMS + reduce ---------
// Block = 32x8 threads, computes a 32x32 tile of g-space (size (H-2)x(W-2)).
// Gray tile 36x36 (halo 2, zeros outside image = reference's zero padding),
// median tile 34x34 in smem, both images in the same block.
__global__ void __launch_bounds__(256) gms_kernel(int s, int H, int W) {
    __shared__ float sA[36][37];
    __shared__ float sB[36][37];
    __shared__ float mA[34][35];
    __shared__ float mB[34][35];

    const int b = blockIdx.z;
    const int ox = blockIdx.x * 32;
    const int oy = blockIdx.y * 32;
    const float* gA = gray_ptr(s, 0) + (long)b * H * W;
    const float* gB = gray_ptr(s, 1) + (long)b * H * W;
    const int tid = threadIdx.y * 32 + threadIdx.x;

    // load gray tile with halo (zero pad outside image)
    for (int k = tid; k < 36 * 36; k += 256) {
        int ly = k / 36, lx = k % 36;
        int gy = oy - 1 + ly, gx = ox - 1 + lx;
        bool inb = ((unsigned)gy < (unsigned)H) && ((unsigned)gx < (unsigned)W);
        long off = (long)gy * W + gx;
        sA[ly][lx] = inb ? gA[off] : 0.0f;
        sB[ly][lx] = inb ? gB[off] : 0.0f;
    }
    __syncthreads();

    // median tile (34x34); out-of-image entries computed but never used
    for (int k = tid; k < 34 * 34; k += 256) {
        int my = k / 34, mx = k % 34;
        mA[my][mx] = med9(sA[my][mx],     sA[my][mx + 1],     sA[my][mx + 2],
                          sA[my + 1][mx], sA[my + 1][mx + 1], sA[my + 1][mx + 2],
                          sA[my + 2][mx], sA[my + 2][mx + 1], sA[my + 2][mx + 2]);
        mB[my][mx] = med9(sB[my][mx],     sB[my][mx + 1],     sB[my][mx + 2],
                          sB[my + 1][mx], sB[my + 1][mx + 1], sB[my + 1][mx + 2],
                          sB[my + 2][mx], sB[my + 2][mx + 1], sB[my + 2][mx + 2]);
    }
    __syncthreads();

    // Prewitt (VALID) + GMS term
    float local = 0.0f;
    const int gx_ = ox + threadIdx.x;
    const float inv3 = 1.0f / 3.0f;
    if (gx_ < W - 2) {
        const int tx = threadIdx.x;
        for (int r = threadIdx.y; r < 32; r += 8) {
            int gy_ = oy + r;
            if (gy_ >= H - 2) break;

            float a00 = mA[r][tx],     a01 = mA[r][tx + 1],     a02 = mA[r][tx + 2];
            float a10 = mA[r + 1][tx],                          a12 = mA[r + 1][tx + 2];
            float a20 = mA[r + 2][tx], a21 = mA[r + 2][tx + 1], a22 = mA[r + 2][tx + 2];
            float axg = (a02 + a12 + a22 - a00 - a10 - a20) * inv3;
            float ayg = (a00 + a01 + a02 - a20 - a21 - a22) * inv3;
            float gi = sqrtf(axg * axg + ayg * ayg);

            float b00 = mB[r][tx],     b01 = mB[r][tx + 1],     b02 = mB[r][tx + 2];
            float b10 = mB[r + 1][tx],                          b12 = mB[r + 1][tx + 2];
            float b20 = mB[r + 2][tx], b21 = mB[r + 2][tx + 1], b22 = mB[r + 2][tx + 2];
            float bxg = (b02 + b12 + b22 - b00 - b10 - b20) * inv3;
            float byg = (b00 + b01 + b02 - b20 - b21 - b22) * inv3;
            float gr = sqrtf(bxg * bxg + byg * byg);

            float gmap = (2.0f * gi * gr + C_GMS) / (gi * gi + gr * gr + C_GMS);
            local += 1.0f - gmap;
        }
    }

    // deterministic block reduction -> fixed slot in d_part
    for (int off = 16; off; off >>= 1)
        local += __shfl_down_sync(0xFFFFFFFFu, local, off);
    __shared__ float ws[8];
    if ((tid & 31) == 0) ws[tid >> 5] = local;
    __syncthreads();
    if (tid == 0) {
        float bs = 0.0f;
        #pragma unroll
        for (int i = 0; i < 8; i++) bs += ws[i];
        int idx = (blockIdx.z * gridDim.y + blockIdx.y) * gridDim.x + blockIdx.x;
        d_part[s][idx] = bs;
    }
}

// ---------------- kernel 4: final deterministic reduction ------------------
__global__ void final_kernel(float* __restrict__ out) {
    __shared__ float sh[256];
    const int t = threadIdx.x;
    const int counts[4] = {16 * 16 * BATCH, 8 * 8 * BATCH, 4 * 4 * BATCH, 2 * 2 * BATCH};
    const float norm[4] = {1.0f / (16.0f * 510 * 510), 1.0f / (16.0f * 254 * 254),
                           1.0f / (16.0f * 126 * 126), 1.0f / (16.0f * 62 * 62)};
    float total = 0.0f;
    for (int sc = 0; sc < 4; sc++) {
        float v = 0.0f;
        for (int i = t; i < counts[sc]; i += 256) v += d_part[sc][i];
        sh[t] = v;
        __syncthreads();
        for (int o = 128; o; o >>= 1) {
            if (t < o) sh[t] += sh[t + o];
            __syncthreads();
        }
        if (t == 0) total += sh[0] * norm[sc];
        __syncthreads();
    }
    if (t == 0) out[0] = total * 0.25f;
}

// ---------------- launch ---------------------------------------------------
extern "C" void kernel_launch(void* const* d_in, const int* in_sizes, int n_in,
                              void* d_out, int out_size) {
    const float* Ii = (const float*)d_in[0];
    const float* Ir = (const float*)d_in[1];

    {   // gray + pool to 256
        int n = BATCH * 256 * 256;
        dim3 g((n + 255) / 256, 1, 2);
        gray_pool_kernel<<<g, 256>>>(Ii, Ir);
    }
    {   // 256 -> 128
        int n = BATCH * 128 * 128;
        dim3 g((n + 255) / 256, 1, 2);
        pool_kernel<<<g, 256>>>(1, 128, 128);
    }
    {   // 128 -> 64
        int n = BATCH * 64 * 64;
        dim3 g((n + 255) / 256, 1, 2);
        pool_kernel<<<g, 256>>>(2, 64, 64);
    }

    const int HS[4] = {512, 256, 128, 64};
    for (int s = 0; s < 4; s++) {
        int H = HS[s], W = HS[s];
        dim3 bl(32, 8);
        dim3 g((W - 2 + 31) / 32, (H - 2 + 31) / 32, BATCH);
        gms_kernel<<<g, bl>>>(s, H, W);
    }

    final_kernel<<<1, 256>>>((float*)d_out);
}

// round 6
// speedup vs baseline: 1.0142x; 1.0142x over previous
#include <cuda_runtime.h>
#include <math.h>

#define BATCH 16
#define C_GMS 0.0026f

// ---------------- scratch (device globals; no allocation allowed) ----------
__device__ float d_g0[2][BATCH * 512 * 512];   // grayscale pyramid, both images
__device__ float d_g1[2][BATCH * 256 * 256];
__device__ float d_g2[2][BATCH * 128 * 128];
__device__ float d_g3[2][BATCH * 64 * 64];
__device__ float d_part[4][4096];              // per-block partial sums per scale

__device__ __forceinline__ float* gray_ptr(int s, int img) {
    switch (s) {
        case 0:  return d_g0[img];
        case 1:  return d_g1[img];
        case 2:  return d_g2[img];
        default: return d_g3[img];
    }
}

// ---------------- kernel 1: grayscale + first 2x2 avg-pool (fused, float4) -
// One thread per 4x2 gray0 patch (= 2 gray1 pixels). 128-bit loads/stores.
__global__ void gray_pool_kernel(const float* __restrict__ Ii,
                                 const float* __restrict__ Ir) {
    const int img = blockIdx.z;
    const float* src = img ? Ir : Ii;
    float* g0 = d_g0[img];
    float* g1 = d_g1[img];

    int i = blockIdx.x * blockDim.x + threadIdx.x;
    if (i >= BATCH * 256 * 128) return;
    int wq = i & 127;          // quad-column (4 g0 cols)
    int t = i >> 7;
    int h2 = t & 255;          // g1 row
    int b = t >> 8;

    const long cs = 512L * 512L;
    const float* p = src + (long)b * 3 * cs + (long)(2 * h2) * 512 + 4 * wq;

    float4 a0 = *(const float4*)(p);
    float4 b0 = *(const float4*)(p + 512);
    float4 a1 = *(const float4*)(p + cs);
    float4 b1 = *(const float4*)(p + cs + 512);
    float4 a2 = *(const float4*)(p + 2 * cs);
    float4 b2 = *(const float4*)(p + 2 * cs + 512);

    const float inv3 = 1.0f / 3.0f;
    float4 r0, r1;
    r0.x = (a0.x + a1.x + a2.x) * inv3;
    r0.y = (a0.y + a1.y + a2.y) * inv3;
    r0.z = (a0.z + a1.z + a2.z) * inv3;
    r0.w = (a0.w + a1.w + a2.w) * inv3;
    r1.x = (b0.x + b1.x + b2.x) * inv3;
    r1.y = (b0.y + b1.y + b2.y) * inv3;
    r1.z = (b0.z + b1.z + b2.z) * inv3;
    r1.w = (b0.w + b1.w + b2.w) * inv3;

    float* q = g0 + ((long)b * 512 + 2 * h2) * 512 + 4 * wq;
    *(float4*)q         = r0;
    *(float4*)(q + 512) = r1;

    float2 o;
    o.x = (r0.x + r0.y + r1.x + r1.y) * 0.25f;
    o.y = (r0.z + r0.w + r1.z + r1.w) * 0.25f;
    *(float2*)(g1 + ((long)b * 256 + h2) * 256 + 2 * wq) = o;
}

// ---------------- kernel 2: generic 2x2 avg-pool on grayscale --------------
__global__ void pool_kernel(int s_in, int Hout, int Wout) {
    const int img = blockIdx.z;
    const float* in = gray_ptr(s_in, img);
    float* out = gray_ptr(s_in + 1, img);

    int i = blockIdx.x * blockDim.x + threadIdx.x;
    int n = BATCH * Hout * Wout;
    if (i >= n) return;
    int w = i % Wout;
    int t = i / Wout;
    int h = t % Hout;
    int b = t / Hout;
    int Win = Wout * 2;

    const float* p = in + ((long)b * Hout * 2 + 2 * h) * Win + 2 * w;
    float2 a = *(const float2*)p;
    float2 c = *(const float2*)(p + Win);
    out[i] = (a.x + a.y + c.x + c.y) * 0.25f;
}

// ---------------- min/max helpers ------------------------------------------
__device__ __forceinline__ void mnmx(float& a, float& b) {
    float t = fminf(a, b);
    b = fmaxf(a, b);
    a = t;
}
__device__ __forceinline__ float med3f(float a, float b, float c) {
    // exact median of 3
    return fmaxf(fminf(a, b), fminf(fmaxf(a, b), c));
}

// ---------------- kernel 3: fused median3 + Prewitt + GMS + reduce ---------
// Block = 32x8 threads, computes a 32x32 tile of g-space (size (H-2)x(W-2)).
// Gray tile 36x36 (halo 2, zeros outside image = reference's zero padding).
// Median pass: column-sort decomposition shared across horizontal runs of 5:
//   med9 = med3( max3(column mins), med3(column medians), min3(column maxs) )
// Prewitt pass: 4 consecutive rows per thread with rolling row sums/diffs.
__global__ void __launch_bounds__(256) gms_kernel(int s, int H, int W) {
    __shared__ float sA[36][37];
    __shared__ float sB[36][37];
    __shared__ float mA[34][35];
    __shared__ float mB[34][35];

    const int b = blockIdx.z;
    const int ox = blockIdx.x * 32;
    const int oy = blockIdx.y * 32;
    const float* gA = gray_ptr(s, 0) + (long)b * H * W;
    const float* gB = gray_ptr(s, 1) + (long)b * H * W;
    const int tid = threadIdx.y * 32 + threadIdx.x;

    // ---- phase 1: load gray tile with halo (zero pad outside image) ----
    for (int k = tid; k < 36 * 36; k += 256) {
        int ly = k / 36, lx = k % 36;
        int gy = oy - 1 + ly, gx = ox - 1 + lx;
        bool inb = ((unsigned)gy < (unsigned)H) && ((unsigned)gx < (unsigned)W);
        long off = (long)gy * W + gx;
        sA[ly][lx] = inb ? gA[off] : 0.0f;
        sB[ly][lx] = inb ? gB[off] : 0.0f;
    }
    __syncthreads();

    // ---- phase 2: median tile (34x34), runs of 5, 7 groups per row ----
    // 34 rows * 7 groups = 238 tasks <= 256 threads -> one task per thread.
    if (tid < 34 * 7) {
        int row = tid / 7;
        int g = tid - row * 7;
        int mx0 = g * 5;
        int wlen = 34 - mx0; if (wlen > 5) wlen = 5;   // last group = 4

        {   // image A
            float lo[7], me[7], hi[7];
            #pragma unroll
            for (int c = 0; c < 7; c++) {
                int col = mx0 + c; if (col > 35) col = 35;
                float x0 = sA[row][col], x1 = sA[row + 1][col], x2 = sA[row + 2][col];
                mnmx(x0, x1); mnmx(x1, x2); mnmx(x0, x1);
                lo[c] = x0; me[c] = x1; hi[c] = x2;
            }
            #pragma unroll
            for (int j = 0; j < 5; j++) {
                if (j < wlen) {
                    float mlo = fmaxf(fmaxf(lo[j], lo[j + 1]), lo[j + 2]);
                    float mhi = fminf(fminf(hi[j], hi[j + 1]), hi[j + 2]);
                    float mme = med3f(me[j], me[j + 1], me[j + 2]);
                    mA[row][mx0 + j] = med3f(mlo, mme, mhi);
                }
            }
        }
        {   // image B
            float lo[7], me[7], hi[7];
            #pragma unroll
            for (int c = 0; c < 7; c++) {
                int col = mx0 + c; if (col > 35) col = 35;
                float x0 = sB[row][col], x1 = sB[row + 1][col], x2 = sB[row + 2][col];
                mnmx(x0, x1); mnmx(x1, x2); mnmx(x0, x1);
                lo[c] = x0; me[c] = x1; hi[c] = x2;
            }
            #pragma unroll
            for (int j = 0; j < 5; j++) {
                if (j < wlen) {
                    float mlo = fmaxf(fmaxf(lo[j], lo[j + 1]), lo[j + 2]);
                    float mhi = fminf(fminf(hi[j], hi[j + 1]), hi[j + 2]);
                    float mme = med3f(me[j], me[j + 1], me[j + 2]);
                    mB[row][mx0 + j] = med3f(mlo, mme, mhi);
                }
            }
        }
    }
    __syncthreads();

    // ---- phase 3: Prewitt (VALID) + GMS, 4 rows per thread, rolling ----
    float local = 0.0f;
    const int tx = threadIdx.x;
    const int gxo = ox + tx;
    const float inv3 = 1.0f / 3.0f;
    if (gxo < W - 2) {
        const int r0 = threadIdx.y * 4;
        float m0, m1, m2;
        // preload rows r0, r0+1 for both images
        m0 = mA[r0][tx]; m1 = mA[r0][tx + 1]; m2 = mA[r0][tx + 2];
        float s0a = m0 + m1 + m2, d0a = m2 - m0;
        m0 = mA[r0 + 1][tx]; m1 = mA[r0 + 1][tx + 1]; m2 = mA[r0 + 1][tx + 2];
        float s1a = m0 + m1 + m2, d1a = m2 - m0;
        m0 = mB[r0][tx]; m1 = mB[r0][tx + 1]; m2 = mB[r0][tx + 2];
        float s0b = m0 + m1 + m2, d0b = m2 - m0;
        m0 = mB[r0 + 1][tx]; m1 = mB[r0 + 1][tx + 1]; m2 = mB[r0 + 1][tx + 2];
        float s1b = m0 + m1 + m2, d1b = m2 - m0;

        #pragma unroll
        for (int i = 0; i < 4; i++) {
            int r = r0 + i;
            if (oy + r >= H - 2) break;

            m0 = mA[r + 2][tx]; m1 = mA[r + 2][tx + 1]; m2 = mA[r + 2][tx + 2];
            float s2a = m0 + m1 + m2, d2a = m2 - m0;
            float gxA = (d0a + d1a + d2a) * inv3;
            float gyA = (s0a - s2a) * inv3;
            float p = gxA * gxA + gyA * gyA;      // gi^2

            m0 = mB[r + 2][tx]; m1 = mB[r + 2][tx + 1]; m2 = mB[r + 2][tx + 2];
            float s2b = m0 + m1 + m2, d2b = m2 - m0;
            float gxB = (d0b + d1b + d2b) * inv3;
            float gyB = (s0b - s2b) * inv3;
            float q = gxB * gxB + gyB * gyB;      // gr^2

            // gmap = (2*gi*gr + c)/(gi^2+gr^2+c); 2*gi*gr = 2*sqrt(p*q)
            float num = 2.0f * sqrtf(p * q) + C_GMS;
            float den = p + q + C_GMS;
            local += 1.0f - __fdividef(num, den);

            s0a = s1a; s1a = s2a; d0a = d1a; d1a = d2a;
            s0b = s1b; s1b = s2b; d0b = d1b; d1b = d2b;
        }
    }

    // ---- deterministic block reduction -> fixed slot in d_part ----
    for (int off = 16; off; off >>= 1)
        local += __shfl_down_sync(0xFFFFFFFFu, local, off);
    __shared__ float ws[8];
    if ((tid & 31) == 0) ws[tid >> 5] = local;
    __syncthreads();
    if (tid == 0) {
        float bs = 0.0f;
        #pragma unroll
        for (int i = 0; i < 8; i++) bs += ws[i];
        int idx = (blockIdx.z * gridDim.y + blockIdx.y) * gridDim.x + blockIdx.x;
        d_part[s][idx] = bs;
    }
}

// ---------------- kernel 4: final deterministic reduction ------------------
__global__ void final_kernel(float* __restrict__ out) {
    __shared__ float sh[256];
    const int t = threadIdx.x;
    const int counts[4] = {16 * 16 * BATCH, 8 * 8 * BATCH, 4 * 4 * BATCH, 2 * 2 * BATCH};
    const float norm[4] = {1.0f / (16.0f * 510 * 510), 1.0f / (16.0f * 254 * 254),
                           1.0f / (16.0f * 126 * 126), 1.0f / (16.0f * 62 * 62)};
    float total = 0.0f;
    for (int sc = 0; sc < 4; sc++) {
        float v = 0.0f;
        for (int i = t; i < counts[sc]; i += 256) v += d_part[sc][i];
        sh[t] = v;
        __syncthreads();
        for (int o = 128; o; o >>= 1) {
            if (t < o) sh[t] += sh[t + o];
            __syncthreads();
        }
        if (t == 0) total += sh[0] * norm[sc];
        __syncthreads();
    }
    if (t == 0) out[0] = total * 0.25f;
}

// ---------------- launch ---------------------------------------------------
extern "C" void kernel_launch(void* const* d_in, const int* in_sizes, int n_in,
                              void* d_out, int out_size) {
    const float* Ii = (const float*)d_in[0];
    const float* Ir = (const float*)d_in[1];

    {   // gray + pool to 256 (float4 path)
        int n = BATCH * 256 * 128;
        dim3 g((n + 255) / 256, 1, 2);
        gray_pool_kernel<<<g, 256>>>(Ii, Ir);
    }
    {   // 256 -> 128
        int n = BATCH * 128 * 128;
        dim3 g((n + 255) / 256, 1, 2);
        pool_kernel<<<g, 256>>>(1, 128, 128);
    }
    {   // 128 -> 64
        int n = BATCH * 64 * 64;
        dim3 g((n + 255) / 256, 1, 2);
        pool_kernel<<<g, 256>>>(2, 64, 64);
    }

    const int HS[4] = {512, 256, 128, 64};
    for (int s = 0; s < 4; s++) {
        int H = HS[s], W = HS[s];
        dim3 bl(32, 8);
        dim3 g((W - 2 + 31) / 32, (H - 2 + 31) / 32, BATCH);
        gms_kernel<<<g, bl>>>(s, H, W);
    }

    final_kernel<<<1, 256>>>((float*)d_out);
}

// round 11
// speedup vs baseline: 1.4408x; 1.4206x over previous
#include <cuda_runtime.h>
#include <math.h>

#define BATCH 16
#define C_GMS 0.0026f

// ---------------- scratch (device globals; no allocation allowed) ----------
__device__ float d_g1[2][BATCH * 256 * 256];   // grayscale pyramid levels 1..3
__device__ float d_g2[2][BATCH * 128 * 128];
__device__ float d_g3[2][BATCH * 64 * 64];
__device__ float d_part[4][4096];              // per-block partial sums per scale

__device__ __forceinline__ float* gray_ptr(int s, int img) {
    switch (s) {
        case 1:  return d_g1[img];
        case 2:  return d_g2[img];
        default: return d_g3[img];
    }
}

// ---------------- min/max helpers ------------------------------------------
__device__ __forceinline__ void mnmx(float& a, float& b) {
    float t = fminf(a, b);
    b = fmaxf(a, b);
    a = t;
}
__device__ __forceinline__ float med3f(float a, float b, float c) {
    return fmaxf(fminf(a, b), fminf(fmaxf(a, b), c));
}

// ---------------- fused kernel: [gray] + median3 + Prewitt + GMS + [pool] ---
// Block = 32x8 threads, one 32x32 tile. Gray tile 36x36 in smem (halo 1 each
// side for the median, +1 for Prewitt; zeros outside image = reference's
// zero padding applied to the *grayscale* image). Median tile 34x34.
//
// s==0: input is RGB [B,3,H,W] (both images), gray computed on the fly.
// s>0 : input is the grayscale pyramid level written by the previous gms call.
// do_pool: write the 2x2 avg-pooled tile interior to the next pyramid level.
//
// Phase-2 task mapping is row-fastest so LDS addresses walk banks at stride
// 5 (37 mod 32) across lanes -> conflict-free.
__global__ void __launch_bounds__(256) gms_kernel(
    int s, int H, int W,
    const float* __restrict__ rgbA, const float* __restrict__ rgbB,
    int do_pool)
{
    __shared__ float sA[36][37];
    __shared__ float sB[36][37];
    __shared__ float mA[34][35];
    __shared__ float mB[34][35];

    const int b = blockIdx.z;
    const int ox = blockIdx.x * 32;
    const int oy = blockIdx.y * 32;
    const int tid = threadIdx.y * 32 + threadIdx.x;
    const float inv3 = 1.0f / 3.0f;

    // ---- phase 1: build gray tile with halo (zero pad outside image) ----
    if (s == 0) {
        const long cs = (long)H * W;
        const float* pA = rgbA + (long)b * 3 * cs;
        const float* pB = rgbB + (long)b * 3 * cs;
        for (int k = tid; k < 36 * 36; k += 256) {
            int ly = k / 36, lx = k - ly * 36;
            int gy = oy - 1 + ly, gx = ox - 1 + lx;
            float va = 0.0f, vb = 0.0f;
            if (((unsigned)gy < (unsigned)H) && ((unsigned)gx < (unsigned)W)) {
                long off = (long)gy * W + gx;
                va = (pA[off] + pA[off + cs] + pA[off + 2 * cs]) * inv3;
                vb = (pB[off] + pB[off + cs] + pB[off + 2 * cs]) * inv3;
            }
            sA[ly][lx] = va;
            sB[ly][lx] = vb;
        }
    } else {
        const float* gA = gray_ptr(s, 0) + (long)b * H * W;
        const float* gB = gray_ptr(s, 1) + (long)b * H * W;
        for (int k = tid; k < 36 * 36; k += 256) {
            int ly = k / 36, lx = k - ly * 36;
            int gy = oy - 1 + ly, gx = ox - 1 + lx;
            bool inb = ((unsigned)gy < (unsigned)H) && ((unsigned)gx < (unsigned)W);
            long off = (long)gy * W + gx;
            sA[ly][lx] = inb ? gA[off] : 0.0f;
            sB[ly][lx] = inb ? gB[off] : 0.0f;
        }
    }
    __syncthreads();

    // ---- pool write: 2x2 avg of tile interior -> next pyramid level ----
    // Tiles are 32-aligned and H,W are multiples of 32, so no halo needed.
    if (do_pool) {
        int j = tid & 15, i = tid >> 4;          // 16x16 pooled outputs
        float pa = (sA[1 + 2 * i][1 + 2 * j] + sA[1 + 2 * i][2 + 2 * j] +
                    sA[2 + 2 * i][1 + 2 * j] + sA[2 + 2 * i][2 + 2 * j]) * 0.25f;
        float pb = (sB[1 + 2 * i][1 + 2 * j] + sB[1 + 2 * i][2 + 2 * j] +
                    sB[2 + 2 * i][1 + 2 * j] + sB[2 + 2 * i][2 + 2 * j]) * 0.25f;
        int Ho = H >> 1, Wo = W >> 1;
        long o = ((long)b * Ho + (oy >> 1) + i) * Wo + (ox >> 1) + j;
        gray_ptr(s + 1, 0)[o] = pa;
        gray_ptr(s + 1, 1)[o] = pb;
    }

    // ---- phase 2: median tile (34x34) via shared column sorts ----
    // Runs of 5 outputs share 7 column sorts:
    //   med9 = med3( max3(col mins), med3(col medians), min3(col maxs) )
    // Row-fastest mapping: row = tid % 34, g = tid / 34 (conflict-free LDS).
    if (tid < 34 * 7) {
        int g = tid / 34;
        int row = tid - g * 34;
        int mx0 = g * 5;
        int wlen = 34 - mx0; if (wlen > 5) wlen = 5;   // last group = 4

        {   // image A
            float lo[7], me[7], hi[7];
            #pragma unroll
            for (int c = 0; c < 7; c++) {
                int col = mx0 + c; if (col > 35) col = 35;
                float x0 = sA[row][col], x1 = sA[row + 1][col], x2 = sA[row + 2][col];
                mnmx(x0, x1); mnmx(x1, x2); mnmx(x0, x1);
                lo[c] = x0; me[c] = x1; hi[c] = x2;
            }
            #pragma unroll
            for (int j = 0; j < 5; j++) {
                if (j < wlen) {
                    float mlo = fmaxf(fmaxf(lo[j], lo[j + 1]), lo[j + 2]);
                    float mhi = fminf(fminf(hi[j], hi[j + 1]), hi[j + 2]);
                    float mme = med3f(me[j], me[j + 1], me[j + 2]);
                    mA[row][mx0 + j] = med3f(mlo, mme, mhi);
                }
            }
        }
        {   // image B
            float lo[7], me[7], hi[7];
            #pragma unroll
            for (int c = 0; c < 7; c++) {
                int col = mx0 + c; if (col > 35) col = 35;
                float x0 = sB[row][col], x1 = sB[row + 1][col], x2 = sB[row + 2][col];
                mnmx(x0, x1); mnmx(x1, x2); mnmx(x0, x1);
                lo[c] = x0; me[c] = x1; hi[c] = x2;
            }
            #pragma unroll
            for (int j = 0; j < 5; j++) {
                if (j < wlen) {
                    float mlo = fmaxf(fmaxf(lo[j], lo[j + 1]), lo[j + 2]);
                    float mhi = fminf(fminf(hi[j], hi[j + 1]), hi[j + 2]);
                    float mme = med3f(me[j], me[j + 1], me[j + 2]);
                    mB[row][mx0 + j] = med3f(mlo, mme, mhi);
                }
            }
        }
    }
    __syncthreads();

    // ---- phase 3: Prewitt (VALID) + GMS, 4 rows per thread, rolling ----
    float local = 0.0f;
    const int tx = threadIdx.x;
    const int gxo = ox + tx;
    if (gxo < W - 2) {
        const int r0 = threadIdx.y * 4;
        float m0, m1, m2;
        m0 = mA[r0][tx]; m1 = mA[r0][tx + 1]; m2 = mA[r0][tx + 2];
        float s0a = m0 + m1 + m2, d0a = m2 - m0;
        m0 = mA[r0 + 1][tx]; m1 = mA[r0 + 1][tx + 1]; m2 = mA[r0 + 1][tx + 2];
        float s1a = m0 + m1 + m2, d1a = m2 - m0;
        m0 = mB[r0][tx]; m1 = mB[r0][tx + 1]; m2 = mB[r0][tx + 2];
        float s0b = m0 + m1 + m2, d0b = m2 - m0;
        m0 = mB[r0 + 1][tx]; m1 = mB[r0 + 1][tx + 1]; m2 = mB[r0 + 1][tx + 2];
        float s1b = m0 + m1 + m2, d1b = m2 - m0;

        #pragma unroll
        for (int i = 0; i < 4; i++) {
            int r = r0 + i;
            if (oy + r >= H - 2) break;

            m0 = mA[r + 2][tx]; m1 = mA[r + 2][tx + 1]; m2 = mA[r + 2][tx + 2];
            float s2a = m0 + m1 + m2, d2a = m2 - m0;
            float gxA = (d0a + d1a + d2a) * inv3;
            float gyA = (s0a - s2a) * inv3;
            float p = gxA * gxA + gyA * gyA;      // gi^2

            m0 = mB[r + 2][tx]; m1 = mB[r + 2][tx + 1]; m2 = mB[r + 2][tx + 2];
            float s2b = m0 + m1 + m2, d2b = m2 - m0;
            float gxB = (d0b + d1b + d2b) * inv3;
            float gyB = (s0b - s2b) * inv3;
            float q = gxB * gxB + gyB * gyB;      // gr^2

            float num = 2.0f * sqrtf(p * q) + C_GMS;
            float den = p + q + C_GMS;
            local += 1.0f - __fdividef(num, den);

            s0a = s1a; s1a = s2a; d0a = d1a; d1a = d2a;
            s0b = s1b; s1b = s2b; d0b = d1b; d1b = d2b;
        }
    }

    // ---- deterministic block reduction -> fixed slot in d_part ----
    for (int off = 16; off; off >>= 1)
        local += __shfl_down_sync(0xFFFFFFFFu, local, off);
    __shared__ float ws[8];
    if ((tid & 31) == 0) ws[tid >> 5] = local;
    __syncthreads();
    if (tid == 0) {
        float bs = 0.0f;
        #pragma unroll
        for (int i = 0; i < 8; i++) bs += ws[i];
        int idx = (blockIdx.z * gridDim.y + blockIdx.y) * gridDim.x + blockIdx.x;
        d_part[s][idx] = bs;
    }
}

// ---------------- final deterministic reduction ----------------------------
__global__ void final_kernel(float* __restrict__ out) {
    __shared__ float sh[256];
    const int t = threadIdx.x;
    const int counts[4] = {16 * 16 * BATCH, 8 * 8 * BATCH, 4 * 4 * BATCH, 2 * 2 * BATCH};
    const float norm[4] = {1.0f / (16.0f * 510 * 510), 1.0f / (16.0f * 254 * 254),
                           1.0f / (16.0f * 126 * 126), 1.0f / (16.0f * 62 * 62)};
    float total = 0.0f;
    for (int sc = 0; sc < 4; sc++) {
        float v = 0.0f;
        for (int i = t; i < counts[sc]; i += 256) v += d_part[sc][i];
        sh[t] = v;
        __syncthreads();
        for (int o = 128; o; o >>= 1) {
            if (t < o) sh[t] += sh[t + o];
            __syncthreads();
        }
        if (t == 0) total += sh[0] * norm[sc];
        __syncthreads();
    }
    if (t == 0) out[0] = total * 0.25f;
}

// ---------------- launch ---------------------------------------------------
extern "C" void kernel_launch(void* const* d_in, const int* in_sizes, int n_in,
                              void* d_out, int out_size) {
    const float* Ii = (const float*)d_in[0];
    const float* Ir = (const float*)d_in[1];

    const int HS[4] = {512, 256, 128, 64};
    for (int s = 0; s < 4; s++) {
        int H = HS[s], W = HS[s];
        dim3 bl(32, 8);
        dim3 g(W / 32, H / 32, BATCH);
        gms_kernel<<<g, bl>>>(s, H, W, Ii, Ir, s < 3 ? 1 : 0);
    }
    final_kernel<<<1, 256>>>((float*)d_out);
}